// round 15
// baseline (speedup 1.0000x reference)
#include <cuda_runtime.h>
#include <cuda_fp16.h>
#include <cstdint>

#define B_  2
#define L_  2048
#define DK_ 512
#define H_  8
#define DH_ 64
#define BH_ (B_*H_)
#define QB_ (L_/128)
#define HSTR 72         // half smem stride for 64-wide tiles  (144 B)
#define PHSTR 136       // half smem stride for 128-wide tiles (272 B)
#define SLABK 1024      // k-columns per slab (2 slabs)

// ---- device scratch ----
__device__ __align__(256) __half g_Qh[BH_*L_*DH_];
__device__ __align__(256) __half g_Kh[BH_*L_*DH_];
__device__ __align__(256) __half g_Vh[BH_*L_*DH_];           // [bh][k][e]; scaled in place
__device__ __align__(256) __half g_Ps[(size_t)BH_*L_*SLABK]; // 64 MiB P slab (reused)
__device__ __align__(256) float  g_Dp[BH_*QB_*L_];

__device__ __forceinline__ float ex2(float x) {
    float r; asm("ex2.approx.f32 %0, %1;" : "=f"(r) : "f"(x));
    return r;
}
__device__ __forceinline__ void mma_f16(float* d, uint32_t a0, uint32_t a1, uint32_t a2,
                                        uint32_t a3, uint32_t b0, uint32_t b1) {
    asm volatile("mma.sync.aligned.m16n8k16.row.col.f32.f16.f16.f32 "
                 "{%0,%1,%2,%3}, {%4,%5,%6,%7}, {%8,%9}, {%0,%1,%2,%3};"
                 : "+f"(d[0]), "+f"(d[1]), "+f"(d[2]), "+f"(d[3])
                 : "r"(a0), "r"(a1), "r"(a2), "r"(a3), "r"(b0), "r"(b1));
}
__device__ __forceinline__ void ldm_x4(uint32_t* r, uint32_t saddr) {
    asm volatile("ldmatrix.sync.aligned.m8n8.x4.shared.b16 {%0,%1,%2,%3}, [%4];"
                 : "=r"(r[0]), "=r"(r[1]), "=r"(r[2]), "=r"(r[3]) : "r"(saddr));
}
__device__ __forceinline__ void ldm_x4t(uint32_t* r, uint32_t saddr) {
    asm volatile("ldmatrix.sync.aligned.m8n8.x4.trans.shared.b16 {%0,%1,%2,%3}, [%4];"
                 : "=r"(r[0]), "=r"(r[1]), "=r"(r[2]), "=r"(r[3]) : "r"(saddr));
}
__device__ __forceinline__ void cp16(void* dst_smem, const void* src) {
    uint32_t d = (uint32_t)__cvta_generic_to_shared(dst_smem);
    asm volatile("cp.async.cg.shared.global [%0], [%1], 16;" :: "r"(d), "l"(src));
}
__device__ __forceinline__ void cp_commit() { asm volatile("cp.async.commit_group;"); }
template<int N> __device__ __forceinline__ void cp_wait() {
    asm volatile("cp.async.wait_group %0;" :: "n"(N));
}
// 4x4 u32 transpose across a lane quad (lanes differing in bits 0-1).
__device__ __forceinline__ void quad_tr(uint32_t x[4], int cp) {
    uint32_t s0 = (cp & 2) ? x[0] : x[2];
    uint32_t s1 = (cp & 2) ? x[1] : x[3];
    uint32_t r0 = __shfl_xor_sync(0xffffffffu, s0, 2);
    uint32_t r1 = __shfl_xor_sync(0xffffffffu, s1, 2);
    if (cp & 2) { x[0] = r0; x[1] = r1; } else { x[2] = r0; x[3] = r1; }
    uint32_t s2 = (cp & 1) ? x[0] : x[1];
    uint32_t s3 = (cp & 1) ? x[2] : x[3];
    uint32_t r2 = __shfl_xor_sync(0xffffffffu, s2, 1);
    uint32_t r3 = __shfl_xor_sync(0xffffffffu, s3, 1);
    if (cp & 1) { x[0] = r2; x[2] = r3; } else { x[1] = r2; x[3] = r3; }
}

// ---------------------------------------------------------------------------
// Unified projections (fp16 mma, fp32 accum).  Q,K,V all -> half.
// ---------------------------------------------------------------------------
__global__ __launch_bounds__(128) void proj_kernel(
    const float* __restrict__ q_in, const float* __restrict__ k_in,
    const float* __restrict__ v_in, const float* __restrict__ wq,
    const float* __restrict__ wk,  const float* __restrict__ wv)
{
    extern __shared__ char smc[];
    __half* Xs = (__half*)smc;       // [128][HSTR]
    __half* Ws = Xs + 128*HSTR;      // [64][HSTR]  (natural W rows: d-major)

    const int mat = blockIdx.z, bh = blockIdx.y, l0 = blockIdx.x * 128;
    const int b = bh / H_, h = bh % H_;
    const float* X = (mat == 0) ? q_in : (mat == 1) ? k_in : v_in;
    const float* W = ((mat == 0) ? wq : (mat == 1) ? wk : wv) + (size_t)h * DK_ * DH_;
    __half* O = (mat == 0) ? g_Qh : (mat == 1) ? g_Kh : g_Vh;

    const int tid = threadIdx.x, lane = tid & 31, wid = tid >> 5;
    const int wm = wid >> 1, wn = wid & 1;
    const int grp = lane >> 2, cp = lane & 3;
    const int xr = tid >> 4, xc = tid & 15;

    float4 xf[16], wf[8];
#pragma unroll
    for (int it = 0; it < 16; ++it)
        xf[it] = *(const float4*)(X + ((size_t)(b * L_ + l0 + xr + it*8)) * DK_ + xc * 4);
#pragma unroll
    for (int it = 0; it < 8; ++it)
        wf[it] = *(const float4*)(W + (size_t)(xr + it*8) * DH_ + xc * 4);

    float acc[4][4][4];
#pragma unroll
    for (int i = 0; i < 4; ++i)
#pragma unroll
        for (int j = 0; j < 4; ++j)
#pragma unroll
            for (int c = 0; c < 4; ++c) acc[i][j][c] = 0.f;

    const uint32_t Xs_u = (uint32_t)__cvta_generic_to_shared(Xs);
    const uint32_t Ws_u = (uint32_t)__cvta_generic_to_shared(Ws);
    const uint32_t a_base = Xs_u + (uint32_t)(wm*64 + (lane & 15)) * (HSTR*2) + (lane >> 4) * 16;
    const uint32_t bt_row = (uint32_t)(lane & 15);
    const uint32_t bt_col = (uint32_t)(wn*32 + ((lane >> 4) & 1) * 8) * 2;

    for (int d0 = 0; d0 < DK_; d0 += 64) {
#pragma unroll
        for (int it = 0; it < 16; ++it) {
            __half2 h01 = __floats2half2_rn(xf[it].x, xf[it].y);
            __half2 h23 = __floats2half2_rn(xf[it].z, xf[it].w);
            *(uint2*)(Xs + (xr + it*8) * HSTR + xc * 4) =
                make_uint2(*(uint32_t*)&h01, *(uint32_t*)&h23);
        }
#pragma unroll
        for (int it = 0; it < 8; ++it) {
            __half2 h01 = __floats2half2_rn(wf[it].x, wf[it].y);
            __half2 h23 = __floats2half2_rn(wf[it].z, wf[it].w);
            *(uint2*)(Ws + (xr + it*8) * HSTR + xc * 4) =
                make_uint2(*(uint32_t*)&h01, *(uint32_t*)&h23);
        }
        __syncthreads();
        if (d0 + 64 < DK_) {
#pragma unroll
            for (int it = 0; it < 16; ++it)
                xf[it] = *(const float4*)(X + ((size_t)(b * L_ + l0 + xr + it*8)) * DK_ + d0 + 64 + xc * 4);
#pragma unroll
            for (int it = 0; it < 8; ++it)
                wf[it] = *(const float4*)(W + (size_t)(d0 + 64 + xr + it*8) * DH_ + xc * 4);
        }
#pragma unroll
        for (int ks = 0; ks < 4; ++ks) {
            uint32_t a[4][4], bf[4][2];
#pragma unroll
            for (int mt = 0; mt < 4; ++mt)
                ldm_x4(a[mt], a_base + mt*16*(HSTR*2) + ks*32);
#pragma unroll
            for (int nb = 0; nb < 2; ++nb) {
                uint32_t bt[4];
                ldm_x4t(bt, Ws_u + (ks*16 + bt_row) * (HSTR*2) + bt_col + nb*32);
                bf[2*nb][0] = bt[0];   bf[2*nb][1] = bt[1];
                bf[2*nb+1][0] = bt[2]; bf[2*nb+1][1] = bt[3];
            }
#pragma unroll
            for (int mt = 0; mt < 4; ++mt)
#pragma unroll
                for (int nt = 0; nt < 4; ++nt)
                    mma_f16(acc[mt][nt], a[mt][0], a[mt][1], a[mt][2], a[mt][3],
                            bf[nt][0], bf[nt][1]);
        }
        __syncthreads();
    }
#pragma unroll
    for (int mt = 0; mt < 4; ++mt) {
        int l = l0 + wm*64 + mt*16 + grp;
#pragma unroll
        for (int nt = 0; nt < 4; ++nt) {
            int e = wn*32 + nt*8 + cp*2;
            *(__half2*)(O + ((size_t)bh*L_ + l)*DH_ + e) =
                __floats2half2_rn(acc[mt][nt][0], acc[mt][nt][1]);
            *(__half2*)(O + ((size_t)bh*L_ + l + 8)*DH_ + e) =
                __floats2half2_rn(acc[mt][nt][2], acc[mt][nt][3]);
        }
    }
}

// ---------------------------------------------------------------------------
// QK^T slab: S over k in [slab*SLABK, slab*SLABK+SLABK).  P -> g_Ps (L2-sized
// slab buffer, default caching).  Block 128q x 256k.  2 CTAs/SM.
// grid (SLABK/256, QB_, BH_).
// ---------------------------------------------------------------------------
__global__ __launch_bounds__(256, 2) void qk_kernel(int slab)
{
    extern __shared__ char smc[];
    __half* Qs = (__half*)smc;              // [128][HSTR]
    __half* Ks = Qs + 128*HSTR;             // [256][HSTR]
    float*  Cs = (float*)(Ks + 256*HSTR);   // [2][128]

    const int bh = blockIdx.z, qb = blockIdx.y, kb = blockIdx.x;
    const int q0 = qb * 128;
    const int k0g = slab * SLABK + kb * 256;   // global k
    const int k0l = kb * 256;                  // k within slab buffer
    const int tid = threadIdx.x, lane = tid & 31, wid = tid >> 5;
    const int wm = wid >> 2, wn = wid & 3;
    const int grp = lane >> 2, cp = lane & 3;

#pragma unroll
    for (int it = 0; it < 4; ++it) {
        int f = it * 256 + tid;
        int r = f >> 3, c8 = f & 7;
        cp16(Qs + r*HSTR + c8*8, g_Qh + ((size_t)bh*L_ + q0 + r)*DH_ + c8*8);
    }
#pragma unroll
    for (int it = 0; it < 8; ++it) {
        int f = it * 256 + tid;
        int r = f >> 3, c8 = f & 7;
        cp16(Ks + r*HSTR + c8*8, g_Kh + ((size_t)bh*L_ + k0g + r)*DH_ + c8*8);
    }
    cp_commit();
    cp_wait<0>();
    __syncthreads();

    const uint32_t Qs_u = (uint32_t)__cvta_generic_to_shared(Qs);
    const uint32_t Ks_u = (uint32_t)__cvta_generic_to_shared(Ks);
    const uint32_t a_base = Qs_u + (uint32_t)(wm*64 + (lane & 15)) * (HSTR*2) + (lane >> 4) * 16;
    const uint32_t b_base0 = Ks_u + (uint32_t)(wn*32 + ((lane >> 4) & 1)*8 + (lane & 7)) * (HSTR*2)
                                  + ((lane >> 3) & 1) * 16;

    const float rsc2 = 0.03188117935f;  // log2(e)/sqrt(2048)

#pragma unroll
    for (int kb2 = 0; kb2 < 2; ++kb2) {
        float acc[4][4][4];
#pragma unroll
        for (int i = 0; i < 4; ++i)
#pragma unroll
            for (int j = 0; j < 4; ++j)
#pragma unroll
                for (int c = 0; c < 4; ++c) acc[i][j][c] = 0.f;

        const uint32_t b_base = b_base0 + (uint32_t)kb2 * 128 * (HSTR*2);
#pragma unroll
        for (int ks = 0; ks < 4; ++ks) {
            uint32_t a[4][4], bf[4][2];
#pragma unroll
            for (int mt = 0; mt < 4; ++mt)
                ldm_x4(a[mt], a_base + mt*16*(HSTR*2) + ks*32);
#pragma unroll
            for (int np = 0; np < 2; ++np) {
                uint32_t bt[4];
                ldm_x4(bt, b_base + np*16*(HSTR*2) + ks*32);
                bf[2*np][0] = bt[0];   bf[2*np][1] = bt[1];
                bf[2*np+1][0] = bt[2]; bf[2*np+1][1] = bt[3];
            }
#pragma unroll
            for (int mt = 0; mt < 4; ++mt)
#pragma unroll
                for (int nt = 0; nt < 4; ++nt)
                    mma_f16(acc[mt][nt], a[mt][0], a[mt][1], a[mt][2], a[mt][3],
                            bf[nt][0], bf[nt][1]);
        }

        float cs0[4] = {0,0,0,0}, cs1[4] = {0,0,0,0};
        const uint32_t kcol = k0l + kb2*128 + wn*32 + cp*8;   // slab-local column
#pragma unroll
        for (int mt = 0; mt < 4; ++mt) {
            int q = q0 + wm*64 + mt*16 + grp;
            uint32_t lo[4], hi[4];
#pragma unroll
            for (int nt = 0; nt < 4; ++nt) {
                float p0 = ex2(acc[mt][nt][0] * rsc2);
                float p1 = ex2(acc[mt][nt][1] * rsc2);
                float p2 = ex2(acc[mt][nt][2] * rsc2);
                float p3 = ex2(acc[mt][nt][3] * rsc2);
                cs0[nt] += p0 + p2;  cs1[nt] += p1 + p3;
                __half2 hl = __floats2half2_rn(p0, p1);
                __half2 hh = __floats2half2_rn(p2, p3);
                lo[nt] = *(uint32_t*)&hl;
                hi[nt] = *(uint32_t*)&hh;
            }
            quad_tr(lo, cp);
            quad_tr(hi, cp);
            *(uint4*)(g_Ps + ((size_t)bh*L_ + q)*SLABK + kcol) =
                make_uint4(lo[0], lo[1], lo[2], lo[3]);
            *(uint4*)(g_Ps + ((size_t)bh*L_ + q + 8)*SLABK + kcol) =
                make_uint4(hi[0], hi[1], hi[2], hi[3]);
        }
#pragma unroll
        for (int nt = 0; nt < 4; ++nt) {
            cs0[nt] += __shfl_xor_sync(0xffffffffu, cs0[nt], 4);
            cs0[nt] += __shfl_xor_sync(0xffffffffu, cs0[nt], 8);
            cs0[nt] += __shfl_xor_sync(0xffffffffu, cs0[nt], 16);
            cs1[nt] += __shfl_xor_sync(0xffffffffu, cs1[nt], 4);
            cs1[nt] += __shfl_xor_sync(0xffffffffu, cs1[nt], 8);
            cs1[nt] += __shfl_xor_sync(0xffffffffu, cs1[nt], 16);
        }
        if (lane < 4) {
#pragma unroll
            for (int nt = 0; nt < 4; ++nt) {
                Cs[wm*128 + wn*32 + nt*8 + lane*2]     = cs0[nt];
                Cs[wm*128 + wn*32 + nt*8 + lane*2 + 1] = cs1[nt];
            }
        }
        __syncthreads();
        if (tid < 128)
            g_Dp[((size_t)bh*QB_ + qb)*L_ + k0g + kb2*128 + tid] = Cs[tid] + Cs[128 + tid];
        __syncthreads();
    }
}

// ---------------------------------------------------------------------------
// dvscale slab: dinv[k] = 1/D[k] (fp32); g_Vh[k][:] *= dinv[k] in place,
// for k in this slab.  grid (SLABK/128, BH_).
// ---------------------------------------------------------------------------
__global__ __launch_bounds__(128) void dvscale_kernel(int slab)
{
    const int bh = blockIdx.y;
    const int k = slab * SLABK + blockIdx.x * 128 + threadIdx.x;

    float s = 0.f;
#pragma unroll
    for (int qt = 0; qt < QB_; ++qt)
        s += g_Dp[((size_t)bh*QB_ + qt)*L_ + k];
    const float dinv = 1.0f / s;

    __half* row = g_Vh + ((size_t)bh*L_ + k)*DH_;
#pragma unroll
    for (int c = 0; c < 8; ++c) {
        uint4 v = *(uint4*)(row + c*8);
        uint32_t* u = (uint32_t*)&v;
#pragma unroll
        for (int j = 0; j < 4; ++j) {
            float2 f = __half22float2(*(__half2*)&u[j]);
            __half2 hr = __floats2half2_rn(f.x * dinv, f.y * dinv);
            u[j] = *(uint32_t*)&hr;
        }
        *(uint4*)(row + c*8) = v;
    }
}

// ---------------------------------------------------------------------------
// PV slab: out (+)= P_slab @ V_slab.  k-chunks of 128 within the slab,
// 2-stage cp.async.  256 threads, warps 4x2, warp tile 32q x 32e.  2 CTAs/SM.
// grid (QB_, BH_).
// ---------------------------------------------------------------------------
__global__ __launch_bounds__(256, 2) void pv_kernel(float* __restrict__ out, int slab)
{
    extern __shared__ char smc[];
    const int STAGE = 128*PHSTR + 128*HSTR;   // halfs per stage
    const int bh = blockIdx.y, q0 = blockIdx.x * 128;
    const int b = bh / H_, h = bh % H_;
    const int tid = threadIdx.x, lane = tid & 31, wid = tid >> 5;
    const int wm = wid >> 1, wn = wid & 1;
    const int grp = lane >> 2, cp = lane & 3;
    const int xr = tid >> 4, xc = tid & 15;

    const __half* Pbase = g_Ps + ((size_t)bh*L_ + q0)*SLABK;        // slab-local
    const __half* Vbase = g_Vh + (size_t)bh*L_*DH_ + (size_t)slab*SLABK*DH_;

    auto fill = [&](int s, int k0) {   // k0 = slab-local
        __half* Ps = (__half*)smc + s*STAGE;
        __half* Vs = Ps + 128*PHSTR;
#pragma unroll
        for (int it = 0; it < 8; ++it) {
            int r = xr + it*16;
            cp16(Ps + r*PHSTR + xc*8, Pbase + (size_t)r*SLABK + k0 + xc*8);
        }
#pragma unroll
        for (int it = 0; it < 4; ++it) {
            int f = it * 256 + tid;
            int r = f >> 3, c = f & 7;
            cp16(Vs + r*HSTR + c*8, Vbase + (size_t)(k0 + r)*DH_ + c*8);
        }
        cp_commit();
    };

    float acc[2][4][4];
#pragma unroll
    for (int i = 0; i < 2; ++i)
#pragma unroll
        for (int j = 0; j < 4; ++j)
#pragma unroll
            for (int c = 0; c < 4; ++c) acc[i][j][c] = 0.f;

    fill(0, 0);

    const uint32_t a_lrow = (uint32_t)(wm*32 + (lane & 15));
    const uint32_t a_csel = (uint32_t)(lane >> 4) * 16;
    const uint32_t bt_row = (uint32_t)(lane & 15);
    const uint32_t bt_col = (uint32_t)(wn*32 + ((lane >> 4) & 1) * 8) * 2;

    for (int it = 0; it < SLABK/128; ++it) {
        int s = it & 1;
        if (it + 1 < SLABK/128) { fill(1 - s, (it + 1) * 128); cp_wait<1>(); }
        else                    { cp_wait<0>(); }
        __syncthreads();

        const __half* Ps = (__half*)smc + s*STAGE;
        const uint32_t Ps_u = (uint32_t)__cvta_generic_to_shared(Ps);
        const uint32_t Vs_u = Ps_u + 128*PHSTR*2;
        const uint32_t a_base = Ps_u + a_lrow * (PHSTR*2) + a_csel;

#pragma unroll
        for (int ks = 0; ks < 8; ++ks) {
            uint32_t a[2][4], bf[4][2];
#pragma unroll
            for (int mt = 0; mt < 2; ++mt)
                ldm_x4(a[mt], a_base + mt*16*(PHSTR*2) + ks*32);
#pragma unroll
            for (int nb = 0; nb < 2; ++nb) {
                uint32_t bt[4];
                ldm_x4t(bt, Vs_u + (ks*16 + bt_row) * (HSTR*2) + bt_col + nb*32);
                bf[2*nb][0] = bt[0];   bf[2*nb][1] = bt[1];
                bf[2*nb+1][0] = bt[2]; bf[2*nb+1][1] = bt[3];
            }
#pragma unroll
            for (int mt = 0; mt < 2; ++mt)
#pragma unroll
                for (int nt = 0; nt < 4; ++nt)
                    mma_f16(acc[mt][nt], a[mt][0], a[mt][1], a[mt][2], a[mt][3],
                            bf[nt][0], bf[nt][1]);
        }
        __syncthreads();
    }
#pragma unroll
    for (int mt = 0; mt < 2; ++mt) {
        int q = q0 + wm*32 + mt*16 + grp;
#pragma unroll
        for (int nt = 0; nt < 4; ++nt) {
            int e = wn*32 + nt*8 + cp*2;
            float* o0 = out + ((size_t)b*L_ + q)*(H_*DH_) + h*DH_ + e;
            float* o1 = out + ((size_t)b*L_ + q + 8)*(H_*DH_) + h*DH_ + e;
            float2 r0 = make_float2(acc[mt][nt][0], acc[mt][nt][1]);
            float2 r1 = make_float2(acc[mt][nt][2], acc[mt][nt][3]);
            if (slab) {
                float2 p0 = *(float2*)o0, p1 = *(float2*)o1;
                r0.x += p0.x; r0.y += p0.y;
                r1.x += p1.x; r1.y += p1.y;
            }
            *(float2*)o0 = r0;
            *(float2*)o1 = r1;
        }
    }
}

// ---------------------------------------------------------------------------
extern "C" void kernel_launch(void* const* d_in, const int* in_sizes, int n_in,
                              void* d_out, int out_size)
{
    const float* keys    = (const float*)d_in[0];
    const float* queries = (const float*)d_in[1];
    const float* values  = (const float*)d_in[2];
    const float* WQ      = (const float*)d_in[3];
    const float* WK      = (const float*)d_in[4];
    const float* WV      = (const float*)d_in[5];
    float* out = (float*)d_out;

    const int QP_SMEM = (128 + 64)*HSTR*2;             // 27648
    const int QK_SMEM = (128 + 256)*HSTR*2 + 256*4;    // 56320
    const int PV_SMEM = 2*(128*PHSTR + 128*HSTR)*2;    // 106496

    cudaFuncSetAttribute(proj_kernel, cudaFuncAttributeMaxDynamicSharedMemorySize, QP_SMEM);
    cudaFuncSetAttribute(qk_kernel,   cudaFuncAttributeMaxDynamicSharedMemorySize, QK_SMEM);
    cudaFuncSetAttribute(pv_kernel,   cudaFuncAttributeMaxDynamicSharedMemorySize, PV_SMEM);

    proj_kernel<<<dim3(L_/128, BH_, 3), 128, QP_SMEM>>>(queries, keys, values, WQ, WK, WV);
    for (int slab = 0; slab < L_/SLABK; ++slab) {
        qk_kernel<<<dim3(SLABK/256, QB_, BH_), 256, QK_SMEM>>>(slab);
        dvscale_kernel<<<dim3(SLABK/128, BH_), 128>>>(slab);
        pv_kernel<<<dim3(QB_, BH_), 256, PV_SMEM>>>(out, slab);
    }
}

// round 16
// speedup vs baseline: 1.0876x; 1.0876x over previous
#include <cuda_runtime.h>
#include <cuda_fp16.h>
#include <cstdint>

#define B_  2
#define L_  2048
#define DK_ 512
#define H_  8
#define DH_ 64
#define BH_ (B_*H_)
#define QB_ (L_/128)
#define HSTR 72         // half smem stride for 64-wide tiles  (144 B)
#define PHSTR 136       // half smem stride for 128-wide tiles (272 B)

// ---- device scratch ----
__device__ __align__(256) __half g_Qh[BH_*L_*DH_];
__device__ __align__(256) __half g_Kh[BH_*L_*DH_];
__device__ __align__(256) __half g_Vh[BH_*L_*DH_];         // [bh][k][e]; scaled in place
__device__ __align__(256) __half g_Ph[(size_t)BH_*L_*L_];  // 128 MiB
__device__ __align__(256) float  g_Dp[BH_*QB_*L_];

__device__ __forceinline__ float ex2(float x) {
    float r; asm("ex2.approx.f32 %0, %1;" : "=f"(r) : "f"(x));
    return r;
}
__device__ __forceinline__ void mma_f16(float* d, uint32_t a0, uint32_t a1, uint32_t a2,
                                        uint32_t a3, uint32_t b0, uint32_t b1) {
    asm volatile("mma.sync.aligned.m16n8k16.row.col.f32.f16.f16.f32 "
                 "{%0,%1,%2,%3}, {%4,%5,%6,%7}, {%8,%9}, {%0,%1,%2,%3};"
                 : "+f"(d[0]), "+f"(d[1]), "+f"(d[2]), "+f"(d[3])
                 : "r"(a0), "r"(a1), "r"(a2), "r"(a3), "r"(b0), "r"(b1));
}
__device__ __forceinline__ void ldm_x4(uint32_t* r, uint32_t saddr) {
    asm volatile("ldmatrix.sync.aligned.m8n8.x4.shared.b16 {%0,%1,%2,%3}, [%4];"
                 : "=r"(r[0]), "=r"(r[1]), "=r"(r[2]), "=r"(r[3]) : "r"(saddr));
}
__device__ __forceinline__ void ldm_x4t(uint32_t* r, uint32_t saddr) {
    asm volatile("ldmatrix.sync.aligned.m8n8.x4.trans.shared.b16 {%0,%1,%2,%3}, [%4];"
                 : "=r"(r[0]), "=r"(r[1]), "=r"(r[2]), "=r"(r[3]) : "r"(saddr));
}
__device__ __forceinline__ void cp16(void* dst_smem, const void* src) {
    uint32_t d = (uint32_t)__cvta_generic_to_shared(dst_smem);
    asm volatile("cp.async.cg.shared.global [%0], [%1], 16;" :: "r"(d), "l"(src));
}
__device__ __forceinline__ void cp_commit() { asm volatile("cp.async.commit_group;"); }
template<int N> __device__ __forceinline__ void cp_wait() {
    asm volatile("cp.async.wait_group %0;" :: "n"(N));
}
// 4x4 u32 transpose across a lane quad (lanes differing in bits 0-1).
__device__ __forceinline__ void quad_tr(uint32_t x[4], int cp) {
    uint32_t s0 = (cp & 2) ? x[0] : x[2];
    uint32_t s1 = (cp & 2) ? x[1] : x[3];
    uint32_t r0 = __shfl_xor_sync(0xffffffffu, s0, 2);
    uint32_t r1 = __shfl_xor_sync(0xffffffffu, s1, 2);
    if (cp & 2) { x[0] = r0; x[1] = r1; } else { x[2] = r0; x[3] = r1; }
    uint32_t s2 = (cp & 1) ? x[0] : x[1];
    uint32_t s3 = (cp & 1) ? x[2] : x[3];
    uint32_t r2 = __shfl_xor_sync(0xffffffffu, s2, 1);
    uint32_t r3 = __shfl_xor_sync(0xffffffffu, s3, 1);
    if (cp & 1) { x[0] = r2; x[2] = r3; } else { x[1] = r2; x[3] = r3; }
}

// ---------------------------------------------------------------------------
// Unified projections (fp16 mma, fp32 accum).  Q,K,V all -> half.
// 128 threads, warps 2x2, warp tile 64l x 32e.
// ---------------------------------------------------------------------------
__global__ __launch_bounds__(128) void proj_kernel(
    const float* __restrict__ q_in, const float* __restrict__ k_in,
    const float* __restrict__ v_in, const float* __restrict__ wq,
    const float* __restrict__ wk,  const float* __restrict__ wv)
{
    extern __shared__ char smc[];
    __half* Xs = (__half*)smc;       // [128][HSTR]
    __half* Ws = Xs + 128*HSTR;      // [64][HSTR]  (natural W rows: d-major)

    const int mat = blockIdx.z, bh = blockIdx.y, l0 = blockIdx.x * 128;
    const int b = bh / H_, h = bh % H_;
    const float* X = (mat == 0) ? q_in : (mat == 1) ? k_in : v_in;
    const float* W = ((mat == 0) ? wq : (mat == 1) ? wk : wv) + (size_t)h * DK_ * DH_;
    __half* O = (mat == 0) ? g_Qh : (mat == 1) ? g_Kh : g_Vh;

    const int tid = threadIdx.x, lane = tid & 31, wid = tid >> 5;
    const int wm = wid >> 1, wn = wid & 1;
    const int grp = lane >> 2, cp = lane & 3;
    const int xr = tid >> 4, xc = tid & 15;

    float4 xf[16], wf[8];
#pragma unroll
    for (int it = 0; it < 16; ++it)
        xf[it] = *(const float4*)(X + ((size_t)(b * L_ + l0 + xr + it*8)) * DK_ + xc * 4);
#pragma unroll
    for (int it = 0; it < 8; ++it)
        wf[it] = *(const float4*)(W + (size_t)(xr + it*8) * DH_ + xc * 4);

    float acc[4][4][4];
#pragma unroll
    for (int i = 0; i < 4; ++i)
#pragma unroll
        for (int j = 0; j < 4; ++j)
#pragma unroll
            for (int c = 0; c < 4; ++c) acc[i][j][c] = 0.f;

    const uint32_t Xs_u = (uint32_t)__cvta_generic_to_shared(Xs);
    const uint32_t Ws_u = (uint32_t)__cvta_generic_to_shared(Ws);
    const uint32_t a_base = Xs_u + (uint32_t)(wm*64 + (lane & 15)) * (HSTR*2) + (lane >> 4) * 16;
    const uint32_t bt_row = (uint32_t)(lane & 15);
    const uint32_t bt_col = (uint32_t)(wn*32 + ((lane >> 4) & 1) * 8) * 2;

    for (int d0 = 0; d0 < DK_; d0 += 64) {
#pragma unroll
        for (int it = 0; it < 16; ++it) {
            __half2 h01 = __floats2half2_rn(xf[it].x, xf[it].y);
            __half2 h23 = __floats2half2_rn(xf[it].z, xf[it].w);
            *(uint2*)(Xs + (xr + it*8) * HSTR + xc * 4) =
                make_uint2(*(uint32_t*)&h01, *(uint32_t*)&h23);
        }
#pragma unroll
        for (int it = 0; it < 8; ++it) {
            __half2 h01 = __floats2half2_rn(wf[it].x, wf[it].y);
            __half2 h23 = __floats2half2_rn(wf[it].z, wf[it].w);
            *(uint2*)(Ws + (xr + it*8) * HSTR + xc * 4) =
                make_uint2(*(uint32_t*)&h01, *(uint32_t*)&h23);
        }
        __syncthreads();
        if (d0 + 64 < DK_) {
#pragma unroll
            for (int it = 0; it < 16; ++it)
                xf[it] = *(const float4*)(X + ((size_t)(b * L_ + l0 + xr + it*8)) * DK_ + d0 + 64 + xc * 4);
#pragma unroll
            for (int it = 0; it < 8; ++it)
                wf[it] = *(const float4*)(W + (size_t)(d0 + 64 + xr + it*8) * DH_ + xc * 4);
        }
#pragma unroll
        for (int ks = 0; ks < 4; ++ks) {
            uint32_t a[4][4], bf[4][2];
#pragma unroll
            for (int mt = 0; mt < 4; ++mt)
                ldm_x4(a[mt], a_base + mt*16*(HSTR*2) + ks*32);
#pragma unroll
            for (int nb = 0; nb < 2; ++nb) {
                uint32_t bt[4];
                ldm_x4t(bt, Ws_u + (ks*16 + bt_row) * (HSTR*2) + bt_col + nb*32);
                bf[2*nb][0] = bt[0];   bf[2*nb][1] = bt[1];
                bf[2*nb+1][0] = bt[2]; bf[2*nb+1][1] = bt[3];
            }
#pragma unroll
            for (int mt = 0; mt < 4; ++mt)
#pragma unroll
                for (int nt = 0; nt < 4; ++nt)
                    mma_f16(acc[mt][nt], a[mt][0], a[mt][1], a[mt][2], a[mt][3],
                            bf[nt][0], bf[nt][1]);
        }
        __syncthreads();
    }
#pragma unroll
    for (int mt = 0; mt < 4; ++mt) {
        int l = l0 + wm*64 + mt*16 + grp;
#pragma unroll
        for (int nt = 0; nt < 4; ++nt) {
            int e = wn*32 + nt*8 + cp*2;
            *(__half2*)(O + ((size_t)bh*L_ + l)*DH_ + e) =
                __floats2half2_rn(acc[mt][nt][0], acc[mt][nt][1]);
            *(__half2*)(O + ((size_t)bh*L_ + l + 8)*DH_ + e) =
                __floats2half2_rn(acc[mt][nt][2], acc[mt][nt][3]);
        }
    }
}

// ---------------------------------------------------------------------------
// QK^T (fp16 mma + ldmatrix) + exp2 + coalesced P stores + column sums.
// Block 128q x 256k, 256 threads, warps 2x4, two k-halves.  2 CTAs/SM.
// ---------------------------------------------------------------------------
__global__ __launch_bounds__(256, 2) void qk_kernel()
{
    extern __shared__ char smc[];
    __half* Qs = (__half*)smc;              // [128][HSTR]
    __half* Ks = Qs + 128*HSTR;             // [256][HSTR]
    float*  Cs = (float*)(Ks + 256*HSTR);   // [2][128]

    const int bh = blockIdx.z, qb = blockIdx.y, kb = blockIdx.x;
    const int q0 = qb * 128, k0 = kb * 256;
    const int tid = threadIdx.x, lane = tid & 31, wid = tid >> 5;
    const int wm = wid >> 2, wn = wid & 3;
    const int grp = lane >> 2, cp = lane & 3;

#pragma unroll
    for (int it = 0; it < 4; ++it) {
        int f = it * 256 + tid;
        int r = f >> 3, c8 = f & 7;
        cp16(Qs + r*HSTR + c8*8, g_Qh + ((size_t)bh*L_ + q0 + r)*DH_ + c8*8);
    }
#pragma unroll
    for (int it = 0; it < 8; ++it) {
        int f = it * 256 + tid;
        int r = f >> 3, c8 = f & 7;
        cp16(Ks + r*HSTR + c8*8, g_Kh + ((size_t)bh*L_ + k0 + r)*DH_ + c8*8);
    }
    cp_commit();
    cp_wait<0>();
    __syncthreads();

    const uint32_t Qs_u = (uint32_t)__cvta_generic_to_shared(Qs);
    const uint32_t Ks_u = (uint32_t)__cvta_generic_to_shared(Ks);
    const uint32_t a_base = Qs_u + (uint32_t)(wm*64 + (lane & 15)) * (HSTR*2) + (lane >> 4) * 16;
    const uint32_t b_base0 = Ks_u + (uint32_t)(wn*32 + ((lane >> 4) & 1)*8 + (lane & 7)) * (HSTR*2)
                                  + ((lane >> 3) & 1) * 16;

    const float rsc2 = 0.03188117935f;  // log2(e)/sqrt(2048)

#pragma unroll
    for (int kb2 = 0; kb2 < 2; ++kb2) {
        float acc[4][4][4];
#pragma unroll
        for (int i = 0; i < 4; ++i)
#pragma unroll
            for (int j = 0; j < 4; ++j)
#pragma unroll
                for (int c = 0; c < 4; ++c) acc[i][j][c] = 0.f;

        const uint32_t b_base = b_base0 + (uint32_t)kb2 * 128 * (HSTR*2);
#pragma unroll
        for (int ks = 0; ks < 4; ++ks) {
            uint32_t a[4][4], bf[4][2];
#pragma unroll
            for (int mt = 0; mt < 4; ++mt)
                ldm_x4(a[mt], a_base + mt*16*(HSTR*2) + ks*32);
#pragma unroll
            for (int np = 0; np < 2; ++np) {
                uint32_t bt[4];
                ldm_x4(bt, b_base + np*16*(HSTR*2) + ks*32);
                bf[2*np][0] = bt[0];   bf[2*np][1] = bt[1];
                bf[2*np+1][0] = bt[2]; bf[2*np+1][1] = bt[3];
            }
#pragma unroll
            for (int mt = 0; mt < 4; ++mt)
#pragma unroll
                for (int nt = 0; nt < 4; ++nt)
                    mma_f16(acc[mt][nt], a[mt][0], a[mt][1], a[mt][2], a[mt][3],
                            bf[nt][0], bf[nt][1]);
        }

        float cs0[4] = {0,0,0,0}, cs1[4] = {0,0,0,0};
        const uint32_t kcol = k0 + kb2*128 + wn*32 + cp*8;
#pragma unroll
        for (int mt = 0; mt < 4; ++mt) {
            int q = q0 + wm*64 + mt*16 + grp;
            uint32_t lo[4], hi[4];
#pragma unroll
            for (int nt = 0; nt < 4; ++nt) {
                float p0 = ex2(acc[mt][nt][0] * rsc2);
                float p1 = ex2(acc[mt][nt][1] * rsc2);
                float p2 = ex2(acc[mt][nt][2] * rsc2);
                float p3 = ex2(acc[mt][nt][3] * rsc2);
                cs0[nt] += p0 + p2;  cs1[nt] += p1 + p3;
                __half2 hl = __floats2half2_rn(p0, p1);
                __half2 hh = __floats2half2_rn(p2, p3);
                lo[nt] = *(uint32_t*)&hl;
                hi[nt] = *(uint32_t*)&hh;
            }
            quad_tr(lo, cp);
            quad_tr(hi, cp);
            __stcs((uint4*)(g_Ph + ((size_t)bh*L_ + q)*L_ + kcol),
                   make_uint4(lo[0], lo[1], lo[2], lo[3]));
            __stcs((uint4*)(g_Ph + ((size_t)bh*L_ + q + 8)*L_ + kcol),
                   make_uint4(hi[0], hi[1], hi[2], hi[3]));
        }
#pragma unroll
        for (int nt = 0; nt < 4; ++nt) {
            cs0[nt] += __shfl_xor_sync(0xffffffffu, cs0[nt], 4);
            cs0[nt] += __shfl_xor_sync(0xffffffffu, cs0[nt], 8);
            cs0[nt] += __shfl_xor_sync(0xffffffffu, cs0[nt], 16);
            cs1[nt] += __shfl_xor_sync(0xffffffffu, cs1[nt], 4);
            cs1[nt] += __shfl_xor_sync(0xffffffffu, cs1[nt], 8);
            cs1[nt] += __shfl_xor_sync(0xffffffffu, cs1[nt], 16);
        }
        if (lane < 4) {
#pragma unroll
            for (int nt = 0; nt < 4; ++nt) {
                Cs[wm*128 + wn*32 + nt*8 + lane*2]     = cs0[nt];
                Cs[wm*128 + wn*32 + nt*8 + lane*2 + 1] = cs1[nt];
            }
        }
        __syncthreads();
        if (tid < 128)
            g_Dp[((size_t)bh*QB_ + qb)*L_ + k0 + kb2*128 + tid] = Cs[tid] + Cs[128 + tid];
        __syncthreads();
    }
}

// ---------------------------------------------------------------------------
// dvscale: dinv[k] = 1/D[k] (fp32), then g_Vh[k][:] *= dinv[k] in place.
// ---------------------------------------------------------------------------
__global__ __launch_bounds__(128) void dvscale_kernel()
{
    const int bh = blockIdx.y, k0 = blockIdx.x * 128;
    const int tid = threadIdx.x;
    const int k = k0 + tid;

    float s = 0.f;
#pragma unroll
    for (int qt = 0; qt < QB_; ++qt)
        s += g_Dp[((size_t)bh*QB_ + qt)*L_ + k];
    const float dinv = 1.0f / s;

    __half* row = g_Vh + ((size_t)bh*L_ + k)*DH_;
#pragma unroll
    for (int c = 0; c < 8; ++c) {
        uint4 v = *(uint4*)(row + c*8);
        uint32_t* u = (uint32_t*)&v;
#pragma unroll
        for (int j = 0; j < 4; ++j) {
            float2 f = __half22float2(*(__half2*)&u[j]);
            __half2 hr = __floats2half2_rn(f.x * dinv, f.y * dinv);
            u[j] = *(uint32_t*)&hr;
        }
        *(uint4*)(row + c*8) = v;
    }
}

// ---------------------------------------------------------------------------
// PV (fp16 mma): out[128q x 64e] = P @ V, V natural [k][e] via ldmatrix.trans.
// k-chunks of 128 processed in ROTATED order per block (de-phases co-resident
// CTAs so fill and compute phases interleave across CTAs).  2-stage cp.async.
// 256 threads, warps 4x2, warp tile 32q x 32e.  2 CTAs/SM.
// ---------------------------------------------------------------------------
__global__ __launch_bounds__(256, 2) void pv_kernel(float* __restrict__ out)
{
    extern __shared__ char smc[];
    const int STAGE = 128*PHSTR + 128*HSTR;   // halfs per stage
    const int bh = blockIdx.y, q0 = blockIdx.x * 128;
    const int b = bh / H_, h = bh % H_;
    const int tid = threadIdx.x, lane = tid & 31, wid = tid >> 5;
    const int wm = wid >> 1, wn = wid & 1;
    const int grp = lane >> 2, cp = lane & 3;
    const int xr = tid >> 4, xc = tid & 15;

    // rotation: co-resident CTAs (bid, bid+148) differ in bit 2 of blockIdx.x
    // (148 % 16 == 4), so they start 4-8 chunks apart and de-phase.
    const int rot = ((blockIdx.x >> 2) & 3) * 4;

    const __half* Pbase = g_Ph + ((size_t)bh*L_ + q0)*L_;
    const __half* Vbase = g_Vh + (size_t)bh*L_*DH_;

    auto fill = [&](int s, int chunk) {
        __half* Ps = (__half*)smc + s*STAGE;
        __half* Vs = Ps + 128*PHSTR;
        const int k0 = chunk * 128;
#pragma unroll
        for (int it = 0; it < 8; ++it) {
            int r = xr + it*16;
            cp16(Ps + r*PHSTR + xc*8, Pbase + (size_t)r*L_ + k0 + xc*8);
        }
#pragma unroll
        for (int it = 0; it < 4; ++it) {
            int f = it * 256 + tid;
            int r = f >> 3, c = f & 7;
            cp16(Vs + r*HSTR + c*8, Vbase + (size_t)(k0 + r)*DH_ + c*8);
        }
        cp_commit();
    };

    float acc[2][4][4];
#pragma unroll
    for (int i = 0; i < 2; ++i)
#pragma unroll
        for (int j = 0; j < 4; ++j)
#pragma unroll
            for (int c = 0; c < 4; ++c) acc[i][j][c] = 0.f;

    fill(0, rot & 15);

    const uint32_t a_lrow = (uint32_t)(wm*32 + (lane & 15));
    const uint32_t a_csel = (uint32_t)(lane >> 4) * 16;
    const uint32_t bt_row = (uint32_t)(lane & 15);
    const uint32_t bt_col = (uint32_t)(wn*32 + ((lane >> 4) & 1) * 8) * 2;

    for (int it = 0; it < L_/128; ++it) {
        int s = it & 1;
        if (it + 1 < L_/128) { fill(1 - s, (it + 1 + rot) & 15); cp_wait<1>(); }
        else                 { cp_wait<0>(); }
        __syncthreads();

        const __half* Ps = (__half*)smc + s*STAGE;
        const uint32_t Ps_u = (uint32_t)__cvta_generic_to_shared(Ps);
        const uint32_t Vs_u = Ps_u + 128*PHSTR*2;
        const uint32_t a_base = Ps_u + a_lrow * (PHSTR*2) + a_csel;

#pragma unroll
        for (int ks = 0; ks < 8; ++ks) {
            uint32_t a[2][4], bf[4][2];
#pragma unroll
            for (int mt = 0; mt < 2; ++mt)
                ldm_x4(a[mt], a_base + mt*16*(PHSTR*2) + ks*32);
#pragma unroll
            for (int nb = 0; nb < 2; ++nb) {
                uint32_t bt[4];
                ldm_x4t(bt, Vs_u + (ks*16 + bt_row) * (HSTR*2) + bt_col + nb*32);
                bf[2*nb][0] = bt[0];   bf[2*nb][1] = bt[1];
                bf[2*nb+1][0] = bt[2]; bf[2*nb+1][1] = bt[3];
            }
#pragma unroll
            for (int mt = 0; mt < 2; ++mt)
#pragma unroll
                for (int nt = 0; nt < 4; ++nt)
                    mma_f16(acc[mt][nt], a[mt][0], a[mt][1], a[mt][2], a[mt][3],
                            bf[nt][0], bf[nt][1]);
        }
        __syncthreads();
    }
#pragma unroll
    for (int mt = 0; mt < 2; ++mt) {
        int q = q0 + wm*32 + mt*16 + grp;
#pragma unroll
        for (int nt = 0; nt < 4; ++nt) {
            int e = wn*32 + nt*8 + cp*2;
            *(float2*)(out + ((size_t)b*L_ + q)*(H_*DH_) + h*DH_ + e) =
                make_float2(acc[mt][nt][0], acc[mt][nt][1]);
            *(float2*)(out + ((size_t)b*L_ + q + 8)*(H_*DH_) + h*DH_ + e) =
                make_float2(acc[mt][nt][2], acc[mt][nt][3]);
        }
    }
}

// ---------------------------------------------------------------------------
extern "C" void kernel_launch(void* const* d_in, const int* in_sizes, int n_in,
                              void* d_out, int out_size)
{
    const float* keys    = (const float*)d_in[0];
    const float* queries = (const float*)d_in[1];
    const float* values  = (const float*)d_in[2];
    const float* WQ      = (const float*)d_in[3];
    const float* WK      = (const float*)d_in[4];
    const float* WV      = (const float*)d_in[5];
    float* out = (float*)d_out;

    const int QP_SMEM = (128 + 64)*HSTR*2;             // 27648
    const int QK_SMEM = (128 + 256)*HSTR*2 + 256*4;    // 56320
    const int PV_SMEM = 2*(128*PHSTR + 128*HSTR)*2;    // 106496

    cudaFuncSetAttribute(proj_kernel, cudaFuncAttributeMaxDynamicSharedMemorySize, QP_SMEM);
    cudaFuncSetAttribute(qk_kernel,   cudaFuncAttributeMaxDynamicSharedMemorySize, QK_SMEM);
    cudaFuncSetAttribute(pv_kernel,   cudaFuncAttributeMaxDynamicSharedMemorySize, PV_SMEM);

    proj_kernel<<<dim3(L_/128, BH_, 3), 128, QP_SMEM>>>(queries, keys, values, WQ, WK, WV);
    qk_kernel<<<dim3(L_/256, L_/128, BH_), 256, QK_SMEM>>>();
    dvscale_kernel<<<dim3(L_/128, BH_), 128>>>();
    pv_kernel<<<dim3(L_/128, BH_), 256, PV_SMEM>>>(out);
}